// round 13
// baseline (speedup 1.0000x reference)
#include <cuda_runtime.h>
#include <cuda_fp16.h>
#include <math.h>
#include <stdint.h>

// ---------------- problem constants ----------------
#define BATCH 4
#define NY    16384
#define NX    4096
#define CY    128
#define CX    256
#define DIM   384        // CY + CX
#define C1    512
#define C2    256
#define C3    128
#define MROWS 65536      // BATCH * NY
#define GRIDM 512        // MROWS / 128

// ---------------- scratch (static device allocations only) ----------------
__device__ __align__(256) __half g_X [(size_t)MROWS * C1];   // fp16 layer input (reused)
__device__ __align__(256) float  g_T [(size_t)MROWS * C1];   // fp32 raw layer output (reused)
__device__ __align__(256) float  g_ps [GRIDM * C1];
__device__ __align__(256) float  g_pq [GRIDM * C1];
__device__ __align__(256) float  g_sc1[C1], g_sh1[C1];
__device__ __align__(256) float  g_sc2[C2], g_sh2[C2];
__device__ __align__(256) float  g_sc3[C3], g_sh3[C3];
__device__ __align__(256) __half g_W1[C1 * DIM];
__device__ __align__(256) __half g_W2[C2 * C1];
__device__ __align__(256) __half g_W3[C3 * C2];

// ---------------- helpers ----------------
__device__ __forceinline__ uint32_t s2u(const void* p) {
    uint32_t a;
    asm("{ .reg .u64 t; cvta.to.shared.u64 t, %1; cvt.u32.u64 %0, t; }" : "=r"(a) : "l"(p));
    return a;
}

#define CP16(dst, src) \
    asm volatile("cp.async.cg.shared.global [%0], [%1], 16;" :: "r"(dst), "l"(src) : "memory")
#define CP_COMMIT() asm volatile("cp.async.commit_group;" ::: "memory")
#define CP_WAIT1()  asm volatile("cp.async.wait_group 1;" ::: "memory")
#define CP_WAIT0()  asm volatile("cp.async.wait_group 0;" ::: "memory")

#define LDMX4(r, addr) \
    asm volatile("ldmatrix.sync.aligned.m8n8.x4.shared.b16 {%0,%1,%2,%3}, [%4];" \
        : "=r"((r)[0]), "=r"((r)[1]), "=r"((r)[2]), "=r"((r)[3]) : "r"(addr))

#define MMA_FP16(d, a, b) \
    asm volatile("mma.sync.aligned.m16n8k16.row.col.f32.f16.f16.f32 " \
        "{%0,%1,%2,%3}, {%4,%5,%6,%7}, {%8,%9}, {%0,%1,%2,%3};" \
        : "+f"((d)[0]), "+f"((d)[1]), "+f"((d)[2]), "+f"((d)[3]) \
        : "r"((a)[0]), "r"((a)[1]), "r"((a)[2]), "r"((a)[3]), "r"((b)[0]), "r"((b)[1]))

// ---------------- fused KNN (K=3, exact reference arithmetic) + gather ----------------
__global__ __launch_bounds__(512) void knn_gather_kernel(
    const float* __restrict__ y_points, const float* __restrict__ x_points,
    const float* __restrict__ y_feats, const float* __restrict__ x_feats,
    __half* __restrict__ X)
{
    __shared__ float4 sxp[NX];                 // 64 KB  {x0, x1, x2, |x|^2}
    __shared__ float  md[9][128];
    __shared__ unsigned short mi[9][128];
    __shared__ unsigned short sidx[3][128];
    __shared__ float  sw[3][128];

    const int tid  = threadIdx.x;
    const int yloc = tid & 127;
    const int q    = tid >> 7;          // 0..3
    const int m0   = blockIdx.x * 128;
    const int b    = m0 / NY;
    const float* xb = x_points + (size_t)b * NX * 3;

    for (int j = tid; j < NX; j += 512) {
        const float x0 = xb[3 * j + 0];
        const float x1 = xb[3 * j + 1];
        const float x2 = xb[3 * j + 2];
        const float xs = __fadd_rn(__fadd_rn(__fmul_rn(x0, x0), __fmul_rn(x1, x1)), __fmul_rn(x2, x2));
        sxp[j] = make_float4(x0, x1, x2, xs);
    }
    __syncthreads();

    const int m = m0 + yloc;
    const float py0 = y_points[(size_t)m * 3 + 0];
    const float py1 = y_points[(size_t)m * 3 + 1];
    const float py2 = y_points[(size_t)m * 3 + 2];
    const float yy = __fadd_rn(__fadd_rn(__fmul_rn(py0, py0), __fmul_rn(py1, py1)), __fmul_rn(py2, py2));

    float d0 = 3.4e38f, d1 = 3.4e38f, d2 = 3.4e38f;
    int   i0 = 0, i1 = 0, i2 = 0;

    #define EXD(p) \
        __fsub_rn(__fadd_rn(yy, (p).w), __fmul_rn(2.0f, \
            __fadd_rn(__fadd_rn(__fmul_rn(py0, (p).x), __fmul_rn(py1, (p).y)), __fmul_rn(py2, (p).z))))
    #define INS(dd, jj) do { \
        if (dd < d2) { \
            if (dd < d1) { \
                d2 = d1; i2 = i1; \
                if (dd < d0) { d1 = d0; i1 = i0; d0 = dd; i0 = (jj); } \
                else         { d1 = dd; i1 = (jj); } \
            } else { d2 = dd; i2 = (jj); } \
        } \
    } while (0)

    const int jbeg = q * (NX / 4);
    const float4* pp = &sxp[jbeg];
    for (int it = 0; it < (NX / 4) / 8; it++) {
        const int j = jbeg + it * 8;
        float dv[8];
        #pragma unroll
        for (int u = 0; u < 8; u++) {
            const float4 p = pp[it * 8 + u];
            dv[u] = EXD(p);
        }
        float dmin = dv[0];
        #pragma unroll
        for (int u = 1; u < 8; u++) dmin = fminf(dmin, dv[u]);
        if (dmin < d2) {
            #pragma unroll
            for (int u = 0; u < 8; u++) INS(dv[u], j + u);
        }
    }
    #undef EXD

    if (q > 0) {
        const int qb = (q - 1) * 3;
        md[qb + 0][yloc] = d0; mi[qb + 0][yloc] = (unsigned short)i0;
        md[qb + 1][yloc] = d1; mi[qb + 1][yloc] = (unsigned short)i1;
        md[qb + 2][yloc] = d2; mi[qb + 2][yloc] = (unsigned short)i2;
    }
    __syncthreads();
    if (q == 0) {
        #pragma unroll
        for (int e = 0; e < 9; e++) {
            const float dd = md[e][yloc];
            const int   jj = (int)mi[e][yloc];
            INS(dd, jj);
        }
        const float w0 = __fdiv_rn(1.0f, __fadd_rn(d0, 1e-8f));
        const float w1 = __fdiv_rn(1.0f, __fadd_rn(d1, 1e-8f));
        const float w2 = __fdiv_rn(1.0f, __fadd_rn(d2, 1e-8f));
        const float s  = __fadd_rn(__fadd_rn(w0, w1), w2);
        sidx[0][yloc] = (unsigned short)i0;
        sidx[1][yloc] = (unsigned short)i1;
        sidx[2][yloc] = (unsigned short)i2;
        sw[0][yloc] = __fdiv_rn(w0, s);
        sw[1][yloc] = __fdiv_rn(w1, s);
        sw[2][yloc] = __fdiv_rn(w2, s);
    }
    #undef INS
    __syncthreads();

    // ---- gather + concat + fp16 convert for this block's 128 rows ----
    const int wrp  = tid >> 5;
    const int lane = tid & 31;
    const float* xfb = x_feats + (size_t)b * NX * CX;
    for (int r = wrp; r < 128; r += 16) {
        const int mm = m0 + r;
        __half* xrow = X + (size_t)mm * DIM;
        const float* yf = y_feats + (size_t)mm * CY;
        #pragma unroll
        for (int c = lane; c < CY; c += 32)
            xrow[c] = __float2half_rn(yf[c]);
        const float* p0 = xfb + (size_t)sidx[0][r] * CX;
        const float* p1 = xfb + (size_t)sidx[1][r] * CX;
        const float* p2 = xfb + (size_t)sidx[2][r] * CX;
        const float w0 = sw[0][r], w1 = sw[1][r], w2 = sw[2][r];
        #pragma unroll
        for (int cc = lane; cc < CX; cc += 32) {
            const float f0 = __fmul_rn(w0, p0[cc]);
            const float f1 = __fmul_rn(w1, p1[cc]);
            const float f2 = __fmul_rn(w2, p2[cc]);
            xrow[CY + cc] = __float2half_rn(__fadd_rn(__fadd_rn(f0, f1), f2));
        }
    }
}

// ---------------- weight fp32 -> fp16 ----------------
__global__ void wconv_kernel(const float* __restrict__ W, __half* __restrict__ H, int n)
{
    const int i = blockIdx.x * 256 + threadIdx.x;
    if (i < n) H[i] = __float2half_rn(W[i]);
}

// ---------------- BN+ReLU + fp16 convert: T fp32 -> X fp16 ----------------
template<int NDIM>
__global__ __launch_bounds__(256) void bnconv_kernel(
    const float* __restrict__ T, const float* __restrict__ sc, const float* __restrict__ sh,
    __half* __restrict__ X)
{
    const size_t i4 = (size_t)blockIdx.x * 256 + threadIdx.x;
    float4 v = ((const float4*)T)[i4];
    const int c = (int)((i4 * 4) & (NDIM - 1));
    v.x = fmaxf(fmaf(v.x, sc[c + 0], sh[c + 0]), 0.0f);
    v.y = fmaxf(fmaf(v.y, sc[c + 1], sh[c + 1]), 0.0f);
    v.z = fmaxf(fmaf(v.z, sc[c + 2], sh[c + 2]), 0.0f);
    v.w = fmaxf(fmaf(v.w, sc[c + 3], sh[c + 3]), 0.0f);
    const __half2 h01 = __floats2half2_rn(v.x, v.y);
    const __half2 h23 = __floats2half2_rn(v.z, v.w);
    uint2 o;
    o.x = *(const uint32_t*)&h01;
    o.y = *(const uint32_t*)&h23;
    ((uint2*)X)[i4] = o;
}

// ---------------- fp16 HMMA GEMM: 4 warps, warp tile 64x64, 3 stages, 2 CTAs/SM ----
// ldsm:MMA ratio 1.0 (vs 0.67 for 64x32 warp tile) -> less smem-pipe pressure.
template<int KDIM, int NDIM>
__global__ __launch_bounds__(128, 2) void hmma_gemm(
    const __half* __restrict__ A, const __half* __restrict__ B,
    float* __restrict__ C, float* __restrict__ ps, float* __restrict__ pq)
{
    constexpr int KC    = 64;               // fp16 per k-chunk = 128B rows
    constexpr int NCH   = KDIM / KC;
    constexpr int RS    = 144;              // 128B row + 16B pad (conflict-free ldmatrix)
    constexpr int PIECE = 128 * RS;
    constexpr int STAGE = 2 * PIECE;        // A, B

    extern __shared__ uint8_t smraw[];
    __shared__ float red_s[2][128], red_q[2][128];

    const int tid  = threadIdx.x;
    const int lane = tid & 31, wid = tid >> 5;   // wid 0..3
    const int wm   = wid & 1,  wn  = wid >> 1;   // 2 x 2 warps, 64x64 each
    const int m0   = blockIdx.y * 128, n0 = blockIdx.x * 128;
    const uint32_t smem = s2u(smraw);

    // loader: 1 thread per row, full 128B row for A and B
    const char* Ag = (const char*)(A + (size_t)(m0 + tid) * KDIM);
    const char* Bg = (const char*)(B + (size_t)(n0 + tid) * KDIM);

    auto issue = [&](int c, int st) {
        const uint32_t sa = smem + st * STAGE + tid * RS;
        const char* pa = Ag + c * 128;
        #pragma unroll
        for (int i = 0; i < 8; i++) CP16(sa + i * 16, pa + i * 16);
        const uint32_t sb = sa + PIECE;
        const char* pb = Bg + c * 128;
        #pragma unroll
        for (int i = 0; i < 8; i++) CP16(sb + i * 16, pb + i * 16);
    };

    float acc[4][8][4];
    #pragma unroll
    for (int i = 0; i < 4; i++)
        #pragma unroll
        for (int j = 0; j < 8; j++)
            #pragma unroll
            for (int f = 0; f < 4; f++) acc[i][j][f] = 0.0f;

    const int l07 = lane & 7;
    const int b3  = (lane >> 3) & 1;
    const int b4  = (lane >> 4) & 1;

    auto mma_stage = [&](int st) {
        const uint32_t Ab = smem + st * STAGE;
        const uint32_t Bb = Ab + PIECE;
        #pragma unroll
        for (int ks = 0; ks < 4; ks++) {
            const uint32_t aoff = (uint32_t)(wm * 64 + l07 + b3 * 8) * RS + ks * 32 + b4 * 16;
            const uint32_t boff = (uint32_t)(wn * 64 + l07 + b4 * 8) * RS + ks * 32 + b3 * 16;
            uint32_t bf[16], af[16];
            #pragma unroll
            for (int nb = 0; nb < 4; nb++) LDMX4(bf + nb * 4, Bb + boff + nb * 16 * RS);
            #pragma unroll
            for (int mt = 0; mt < 4; mt++) LDMX4(af + mt * 4, Ab + aoff + mt * 16 * RS);
            #pragma unroll
            for (int mt = 0; mt < 4; mt++)
                #pragma unroll
                for (int nt = 0; nt < 8; nt++)
                    MMA_FP16(acc[mt][nt], af + mt * 4, bf + nt * 2);
        }
    };

    issue(0, 0); CP_COMMIT();
    issue(1, 1); CP_COMMIT();

    for (int c = 0; c < NCH; c++) {
        if (c == NCH - 1) { CP_WAIT0(); } else { CP_WAIT1(); }
        __syncthreads();
        if (c + 2 < NCH) { issue(c + 2, (c + 2) % 3); CP_COMMIT(); }
        mma_stage(c % 3);
    }

    // ---- epilogue: store C + deterministic per-column stats partials ----
    const int g = lane >> 2, q4 = lane & 3;
    float s8[8][2], q8[8][2];
    #pragma unroll
    for (int nt = 0; nt < 8; nt++) { s8[nt][0] = s8[nt][1] = 0.0f; q8[nt][0] = q8[nt][1] = 0.0f; }

    #pragma unroll
    for (int mt = 0; mt < 4; mt++) {
        #pragma unroll
        for (int nt = 0; nt < 8; nt++) {
            const int r = m0 + wm * 64 + mt * 16 + g;
            const int col = n0 + wn * 64 + nt * 8 + q4 * 2;
            float2 v0 = make_float2(acc[mt][nt][0], acc[mt][nt][1]);
            float2 v1 = make_float2(acc[mt][nt][2], acc[mt][nt][3]);
            *(float2*)(C + (size_t)r * NDIM + col)       = v0;
            *(float2*)(C + (size_t)(r + 8) * NDIM + col) = v1;
            s8[nt][0] += v0.x + v1.x;
            s8[nt][1] += v0.y + v1.y;
            q8[nt][0] += v0.x * v0.x + v1.x * v1.x;
            q8[nt][1] += v0.y * v0.y + v1.y * v1.y;
        }
    }
    __syncthreads();
    #pragma unroll
    for (int nt = 0; nt < 8; nt++)
        #pragma unroll
        for (int j = 0; j < 2; j++) {
            float s = s8[nt][j], q = q8[nt][j];
            #pragma unroll
            for (int off = 4; off < 32; off <<= 1) {
                s += __shfl_xor_sync(0xFFFFFFFFu, s, off);
                q += __shfl_xor_sync(0xFFFFFFFFu, q, off);
            }
            if (lane < 4) {
                const int cl = wn * 64 + nt * 8 + lane * 2 + j;
                red_s[wm][cl] = s;
                red_q[wm][cl] = q;
            }
        }
    __syncthreads();
    // all 128 threads: coalesced partial write
    ps[(size_t)blockIdx.y * NDIM + n0 + tid] = red_s[0][tid] + red_s[1][tid];
    pq[(size_t)blockIdx.y * NDIM + n0 + tid] = red_q[0][tid] + red_q[1][tid];
}

// ---------------- BN finalize: reduce partials -> scale/shift (coalesced) ----------------
__global__ void finalize_kernel(
    const float* __restrict__ ps, const float* __restrict__ pq,
    const float* __restrict__ g, const float* __restrict__ be,
    float* __restrict__ sc, float* __restrict__ sh, int N)
{
    const int n = blockIdx.x * 128 + threadIdx.x;
    if (n >= N) return;
    float s = 0.0f, q = 0.0f;
    #pragma unroll 8
    for (int i = 0; i < GRIDM; i++) { s += ps[(size_t)i * N + n]; q += pq[(size_t)i * N + n]; }
    const float mean = s * (1.0f / (float)MROWS);
    const float var  = q * (1.0f / (float)MROWS) - mean * mean;
    const float rstd = rsqrtf(var + 1e-5f);
    const float scale = g[n] * rstd;
    sc[n] = scale;
    sh[n] = be[n] - mean * scale;
}

// ---------------- final BN+ReLU + transpose to [B, C3, NY] ----------------
__global__ __launch_bounds__(256) void output_kernel(
    const float* __restrict__ T3, const float* __restrict__ sc,
    const float* __restrict__ sh, float* __restrict__ out)
{
    __shared__ float tilebuf[32][33];
    const int mt = blockIdx.x * 32;
    const int ct = blockIdx.y * 32;
    const int tx = threadIdx.x;
    const int ty = threadIdx.y;
    #pragma unroll
    for (int i = ty; i < 32; i += 8) {
        const int c = ct + tx;
        const float v = T3[(size_t)(mt + i) * C3 + c];
        tilebuf[i][tx] = fmaxf(v * sc[c] + sh[c], 0.0f);
    }
    __syncthreads();
    const int m  = mt + tx;
    const int b  = m / NY;
    const int ny = m % NY;
    #pragma unroll
    for (int j = ty; j < 32; j += 8) {
        const int c = ct + j;
        out[((size_t)b * C3 + c) * NY + ny] = tilebuf[tx][j];
    }
}

// ---------------- launch ----------------
static void* sym_addr(const void* sym) { void* p = nullptr; cudaGetSymbolAddress(&p, sym); return p; }

extern "C" void kernel_launch(void* const* d_in, const int* in_sizes, int n_in,
                              void* d_out, int out_size)
{
    const float* y_points = (const float*)d_in[0];
    const float* y_feats  = (const float*)d_in[1];
    const float* x_points = (const float*)d_in[2];
    const float* x_feats  = (const float*)d_in[3];
    const float* W1 = (const float*)d_in[4];
    const float* g1 = (const float*)d_in[6];
    const float* be1= (const float*)d_in[7];
    const float* W2 = (const float*)d_in[8];
    const float* g2 = (const float*)d_in[10];
    const float* be2= (const float*)d_in[11];
    const float* W3 = (const float*)d_in[12];
    const float* g3 = (const float*)d_in[14];
    const float* be3= (const float*)d_in[15];
    float* out = (float*)d_out;
    // conv biases b1/b2/b3 cancel exactly through training-mode BN: mean shift
    // absorbs them and variance is unaffected, so they are intentionally unused.

    __half* pX = (__half*)sym_addr(g_X);
    float*  pT = (float*) sym_addr(g_T);
    float* pPs = (float*) sym_addr(g_ps);
    float* pPq = (float*) sym_addr(g_pq);
    float* pSc1= (float*) sym_addr(g_sc1);
    float* pSh1= (float*) sym_addr(g_sh1);
    float* pSc2= (float*) sym_addr(g_sc2);
    float* pSh2= (float*) sym_addr(g_sh2);
    float* pSc3= (float*) sym_addr(g_sc3);
    float* pSh3= (float*) sym_addr(g_sh3);
    __half* pW1h = (__half*)sym_addr(g_W1);
    __half* pW2h = (__half*)sym_addr(g_W2);
    __half* pW3h = (__half*)sym_addr(g_W3);

    constexpr int SMEMSZ = 3 * 2 * 128 * 144;   // 110592: 3 stages x (A, B)
    cudaFuncSetAttribute((const void*)hmma_gemm<DIM, C1>, cudaFuncAttributeMaxDynamicSharedMemorySize, SMEMSZ);
    cudaFuncSetAttribute((const void*)hmma_gemm<C1,  C2>, cudaFuncAttributeMaxDynamicSharedMemorySize, SMEMSZ);
    cudaFuncSetAttribute((const void*)hmma_gemm<C2,  C3>, cudaFuncAttributeMaxDynamicSharedMemorySize, SMEMSZ);

    // launch order puts hmma_gemm<384,512> at index 3 (the profiled slot)
    knn_gather_kernel<<<MROWS / 128, 512>>>(y_points, x_points, y_feats, x_feats, pX); // 0
    wconv_kernel<<<(C1 * DIM + 255) / 256, 256>>>(W1, pW1h, C1 * DIM);                 // 1
    wconv_kernel<<<(C2 * C1 + 255) / 256, 256>>>(W2, pW2h, C2 * C1);                   // 2
    hmma_gemm<DIM, C1><<<dim3(C1 / 128, GRIDM), 128, SMEMSZ>>>(pX, pW1h, pT, pPs, pPq);// 3 <- profiled
    wconv_kernel<<<(C3 * C2 + 255) / 256, 256>>>(W3, pW3h, C3 * C2);                   // 4
    finalize_kernel<<<C1 / 128, 128>>>(pPs, pPq, g1, be1, pSc1, pSh1, C1);             // 5
    bnconv_kernel<C1><<<(size_t)MROWS * C1 / 1024, 256>>>(pT, pSc1, pSh1, pX);         // 6
    hmma_gemm<C1, C2><<<dim3(C2 / 128, GRIDM), 128, SMEMSZ>>>(pX, pW2h, pT, pPs, pPq); // 7
    finalize_kernel<<<C2 / 128, 128>>>(pPs, pPq, g2, be2, pSc2, pSh2, C2);             // 8
    bnconv_kernel<C2><<<(size_t)MROWS * C2 / 1024, 256>>>(pT, pSc2, pSh2, pX);         // 9
    hmma_gemm<C2, C3><<<dim3(C3 / 128, GRIDM), 128, SMEMSZ>>>(pX, pW3h, pT, pPs, pPq); // 10
    finalize_kernel<<<C3 / 128, 128>>>(pPs, pPq, g3, be3, pSc3, pSh3, C3);             // 11
    output_kernel<<<dim3(MROWS / 32, C3 / 32), dim3(32, 8)>>>(pT, pSc3, pSh3, out);    // 12
}

// round 14
// speedup vs baseline: 1.2480x; 1.2480x over previous
#include <cuda_runtime.h>
#include <cuda_fp16.h>
#include <math.h>
#include <stdint.h>

// ---------------- problem constants ----------------
#define BATCH 4
#define NY    16384
#define NX    4096
#define CY    128
#define CX    256
#define DIM   384        // CY + CX
#define C1    512
#define C2    256
#define C3    128
#define MROWS 65536      // BATCH * NY
#define GRIDM 512        // MROWS / 128

// ---------------- scratch (static device allocations only) ----------------
__device__ __align__(256) __half g_X [(size_t)MROWS * C1];   // fp16 layer input (reused)
__device__ __align__(256) float  g_T [(size_t)MROWS * C1];   // fp32 raw layer output (reused)
__device__ __align__(256) float  g_ps [GRIDM * C1];
__device__ __align__(256) float  g_pq [GRIDM * C1];
__device__ __align__(256) float  g_sc1[C1], g_sh1[C1];
__device__ __align__(256) float  g_sc2[C2], g_sh2[C2];
__device__ __align__(256) float  g_sc3[C3], g_sh3[C3];
__device__ __align__(256) __half g_W1[C1 * DIM];
__device__ __align__(256) __half g_W2[C2 * C1];
__device__ __align__(256) __half g_W3[C3 * C2];

// ---------------- helpers ----------------
__device__ __forceinline__ uint32_t s2u(const void* p) {
    uint32_t a;
    asm("{ .reg .u64 t; cvta.to.shared.u64 t, %1; cvt.u32.u64 %0, t; }" : "=r"(a) : "l"(p));
    return a;
}

#define CP16(dst, src) \
    asm volatile("cp.async.cg.shared.global [%0], [%1], 16;" :: "r"(dst), "l"(src) : "memory")
#define CP_COMMIT() asm volatile("cp.async.commit_group;" ::: "memory")
#define CP_WAIT1()  asm volatile("cp.async.wait_group 1;" ::: "memory")
#define CP_WAIT0()  asm volatile("cp.async.wait_group 0;" ::: "memory")

#define LDMX4(r, addr) \
    asm volatile("ldmatrix.sync.aligned.m8n8.x4.shared.b16 {%0,%1,%2,%3}, [%4];" \
        : "=r"((r)[0]), "=r"((r)[1]), "=r"((r)[2]), "=r"((r)[3]) : "r"(addr))

#define MMA_FP16(d, a, b) \
    asm volatile("mma.sync.aligned.m16n8k16.row.col.f32.f16.f16.f32 " \
        "{%0,%1,%2,%3}, {%4,%5,%6,%7}, {%8,%9}, {%0,%1,%2,%3};" \
        : "+f"((d)[0]), "+f"((d)[1]), "+f"((d)[2]), "+f"((d)[3]) \
        : "r"((a)[0]), "r"((a)[1]), "r"((a)[2]), "r"((a)[3]), "r"((b)[0]), "r"((b)[1]))

// ---------------- fused KNN (K=3, exact reference arithmetic) + gather ----------------
__global__ __launch_bounds__(512) void knn_gather_kernel(
    const float* __restrict__ y_points, const float* __restrict__ x_points,
    const float* __restrict__ y_feats, const float* __restrict__ x_feats,
    __half* __restrict__ X)
{
    __shared__ float4 sxp[NX];                 // 64 KB  {x0, x1, x2, |x|^2}
    __shared__ float  md[9][128];
    __shared__ unsigned short mi[9][128];
    __shared__ unsigned short sidx[3][128];
    __shared__ float  sw[3][128];

    const int tid  = threadIdx.x;
    const int yloc = tid & 127;
    const int q    = tid >> 7;          // 0..3
    const int m0   = blockIdx.x * 128;
    const int b    = m0 / NY;
    const float* xb = x_points + (size_t)b * NX * 3;

    for (int j = tid; j < NX; j += 512) {
        const float x0 = xb[3 * j + 0];
        const float x1 = xb[3 * j + 1];
        const float x2 = xb[3 * j + 2];
        const float xs = __fadd_rn(__fadd_rn(__fmul_rn(x0, x0), __fmul_rn(x1, x1)), __fmul_rn(x2, x2));
        sxp[j] = make_float4(x0, x1, x2, xs);
    }
    __syncthreads();

    const int m = m0 + yloc;
    const float py0 = y_points[(size_t)m * 3 + 0];
    const float py1 = y_points[(size_t)m * 3 + 1];
    const float py2 = y_points[(size_t)m * 3 + 2];
    const float yy = __fadd_rn(__fadd_rn(__fmul_rn(py0, py0), __fmul_rn(py1, py1)), __fmul_rn(py2, py2));

    float d0 = 3.4e38f, d1 = 3.4e38f, d2 = 3.4e38f;
    int   i0 = 0, i1 = 0, i2 = 0;

    #define EXD(p) \
        __fsub_rn(__fadd_rn(yy, (p).w), __fmul_rn(2.0f, \
            __fadd_rn(__fadd_rn(__fmul_rn(py0, (p).x), __fmul_rn(py1, (p).y)), __fmul_rn(py2, (p).z))))
    #define INS(dd, jj) do { \
        if (dd < d2) { \
            if (dd < d1) { \
                d2 = d1; i2 = i1; \
                if (dd < d0) { d1 = d0; i1 = i0; d0 = dd; i0 = (jj); } \
                else         { d1 = dd; i1 = (jj); } \
            } else { d2 = dd; i2 = (jj); } \
        } \
    } while (0)

    const int jbeg = q * (NX / 4);
    const float4* pp = &sxp[jbeg];
    for (int it = 0; it < (NX / 4) / 8; it++) {
        const int j = jbeg + it * 8;
        float dv[8];
        #pragma unroll
        for (int u = 0; u < 8; u++) {
            const float4 p = pp[it * 8 + u];
            dv[u] = EXD(p);
        }
        float dmin = dv[0];
        #pragma unroll
        for (int u = 1; u < 8; u++) dmin = fminf(dmin, dv[u]);
        if (dmin < d2) {
            #pragma unroll
            for (int u = 0; u < 8; u++) INS(dv[u], j + u);
        }
    }
    #undef EXD

    if (q > 0) {
        const int qb = (q - 1) * 3;
        md[qb + 0][yloc] = d0; mi[qb + 0][yloc] = (unsigned short)i0;
        md[qb + 1][yloc] = d1; mi[qb + 1][yloc] = (unsigned short)i1;
        md[qb + 2][yloc] = d2; mi[qb + 2][yloc] = (unsigned short)i2;
    }
    __syncthreads();
    if (q == 0) {
        #pragma unroll
        for (int e = 0; e < 9; e++) {
            const float dd = md[e][yloc];
            const int   jj = (int)mi[e][yloc];
            INS(dd, jj);
        }
        const float w0 = __fdiv_rn(1.0f, __fadd_rn(d0, 1e-8f));
        const float w1 = __fdiv_rn(1.0f, __fadd_rn(d1, 1e-8f));
        const float w2 = __fdiv_rn(1.0f, __fadd_rn(d2, 1e-8f));
        const float s  = __fadd_rn(__fadd_rn(w0, w1), w2);
        sidx[0][yloc] = (unsigned short)i0;
        sidx[1][yloc] = (unsigned short)i1;
        sidx[2][yloc] = (unsigned short)i2;
        sw[0][yloc] = __fdiv_rn(w0, s);
        sw[1][yloc] = __fdiv_rn(w1, s);
        sw[2][yloc] = __fdiv_rn(w2, s);
    }
    #undef INS
    __syncthreads();

    // ---- gather + concat + fp16 convert for this block's 128 rows ----
    const int wrp  = tid >> 5;
    const int lane = tid & 31;
    const float* xfb = x_feats + (size_t)b * NX * CX;
    for (int r = wrp; r < 128; r += 16) {
        const int mm = m0 + r;
        __half* xrow = X + (size_t)mm * DIM;
        const float* yf = y_feats + (size_t)mm * CY;
        #pragma unroll
        for (int c = lane; c < CY; c += 32)
            xrow[c] = __float2half_rn(yf[c]);
        const float* p0 = xfb + (size_t)sidx[0][r] * CX;
        const float* p1 = xfb + (size_t)sidx[1][r] * CX;
        const float* p2 = xfb + (size_t)sidx[2][r] * CX;
        const float w0 = sw[0][r], w1 = sw[1][r], w2 = sw[2][r];
        #pragma unroll
        for (int cc = lane; cc < CX; cc += 32) {
            const float f0 = __fmul_rn(w0, p0[cc]);
            const float f1 = __fmul_rn(w1, p1[cc]);
            const float f2 = __fmul_rn(w2, p2[cc]);
            xrow[CY + cc] = __float2half_rn(__fadd_rn(__fadd_rn(f0, f1), f2));
        }
    }
}

// ---------------- weight fp32 -> fp16 ----------------
__global__ void wconv_kernel(const float* __restrict__ W, __half* __restrict__ H, int n)
{
    const int i = blockIdx.x * 256 + threadIdx.x;
    if (i < n) H[i] = __float2half_rn(W[i]);
}

// ---------------- BN+ReLU + fp16 convert: T fp32 -> X fp16 ----------------
template<int NDIM>
__global__ __launch_bounds__(256) void bnconv_kernel(
    const float* __restrict__ T, const float* __restrict__ sc, const float* __restrict__ sh,
    __half* __restrict__ X)
{
    const size_t i4 = (size_t)blockIdx.x * 256 + threadIdx.x;
    float4 v = ((const float4*)T)[i4];
    const int c = (int)((i4 * 4) & (NDIM - 1));
    v.x = fmaxf(fmaf(v.x, sc[c + 0], sh[c + 0]), 0.0f);
    v.y = fmaxf(fmaf(v.y, sc[c + 1], sh[c + 1]), 0.0f);
    v.z = fmaxf(fmaf(v.z, sc[c + 2], sh[c + 2]), 0.0f);
    v.w = fmaxf(fmaf(v.w, sc[c + 3], sh[c + 3]), 0.0f);
    const __half2 h01 = __floats2half2_rn(v.x, v.y);
    const __half2 h23 = __floats2half2_rn(v.z, v.w);
    uint2 o;
    o.x = *(const uint32_t*)&h01;
    o.y = *(const uint32_t*)&h23;
    ((uint2*)X)[i4] = o;
}

// ---------------- fp16 HMMA GEMM, cp.async both operands, 3 stages, 2 CTAs/SM -------
// (R11 config: 256 threads, 8 warps 2Mx4N, warp tile 64x32, 124 regs -> 16 warps/SM)
template<int KDIM, int NDIM>
__global__ __launch_bounds__(256, 2) void hmma_gemm(
    const __half* __restrict__ A, const __half* __restrict__ B,
    float* __restrict__ C, float* __restrict__ ps, float* __restrict__ pq)
{
    constexpr int KC    = 64;               // fp16 per k-chunk = 128B rows
    constexpr int NCH   = KDIM / KC;
    constexpr int RS    = 144;              // 128B row + 16B pad (conflict-free ldmatrix)
    constexpr int PIECE = 128 * RS;
    constexpr int STAGE = 2 * PIECE;        // A, B

    extern __shared__ uint8_t smraw[];
    __shared__ float red_s[2][128], red_q[2][128];

    const int tid  = threadIdx.x;
    const int lane = tid & 31, wid = tid >> 5;
    const int wm   = wid & 1,  wn  = wid >> 1;
    const int m0   = blockIdx.y * 128, n0 = blockIdx.x * 128;
    const uint32_t smem = s2u(smraw);

    const int row  = tid >> 1;
    const int half = tid & 1;
    const char* Ag = (const char*)(A + (size_t)(m0 + row) * KDIM) + half * 64;
    const char* Bg = (const char*)(B + (size_t)(n0 + row) * KDIM) + half * 64;

    auto issue = [&](int c, int st) {
        const uint32_t sa = smem + st * STAGE + row * RS + half * 64;
        const char* pa = Ag + c * 128;
        CP16(sa,      pa);      CP16(sa + 16, pa + 16);
        CP16(sa + 32, pa + 32); CP16(sa + 48, pa + 48);
        const uint32_t sb = sa + PIECE;
        const char* pb = Bg + c * 128;
        CP16(sb,      pb);      CP16(sb + 16, pb + 16);
        CP16(sb + 32, pb + 32); CP16(sb + 48, pb + 48);
    };

    float acc[4][4][4];
    #pragma unroll
    for (int i = 0; i < 4; i++)
        #pragma unroll
        for (int j = 0; j < 4; j++)
            #pragma unroll
            for (int f = 0; f < 4; f++) acc[i][j][f] = 0.0f;

    const int l07 = lane & 7;
    const int b3  = (lane >> 3) & 1;
    const int b4  = (lane >> 4) & 1;

    auto mma_stage = [&](int st) {
        const uint32_t Ab = smem + st * STAGE;
        const uint32_t Bb = Ab + PIECE;
        #pragma unroll
        for (int ks = 0; ks < 4; ks++) {
            const uint32_t aoff = (uint32_t)(wm * 64 + l07 + b3 * 8) * RS + ks * 32 + b4 * 16;
            const uint32_t boff = (uint32_t)(wn * 32 + l07 + b4 * 8) * RS + ks * 32 + b3 * 16;
            uint32_t bf[8], af[16];
            LDMX4(bf,     Bb + boff);
            LDMX4(bf + 4, Bb + boff + 16 * RS);
            #pragma unroll
            for (int mt = 0; mt < 4; mt++) LDMX4(af + mt * 4, Ab + aoff + mt * 16 * RS);
            #pragma unroll
            for (int mt = 0; mt < 4; mt++)
                #pragma unroll
                for (int nt = 0; nt < 4; nt++)
                    MMA_FP16(acc[mt][nt], af + mt * 4, bf + nt * 2);
        }
    };

    issue(0, 0); CP_COMMIT();
    issue(1, 1); CP_COMMIT();

    for (int c = 0; c < NCH; c++) {
        if (c == NCH - 1) { CP_WAIT0(); } else { CP_WAIT1(); }
        __syncthreads();
        if (c + 2 < NCH) { issue(c + 2, (c + 2) % 3); CP_COMMIT(); }
        mma_stage(c % 3);
    }

    // ---- epilogue: store C + deterministic per-column stats partials ----
    const int g = lane >> 2, q4 = lane & 3;
    float s8[4][2], q8[4][2];
    #pragma unroll
    for (int nt = 0; nt < 4; nt++) { s8[nt][0] = s8[nt][1] = 0.0f; q8[nt][0] = q8[nt][1] = 0.0f; }

    #pragma unroll
    for (int mt = 0; mt < 4; mt++) {
        #pragma unroll
        for (int nt = 0; nt < 4; nt++) {
            const int r = m0 + wm * 64 + mt * 16 + g;
            const int col = n0 + wn * 32 + nt * 8 + q4 * 2;
            float2 v0 = make_float2(acc[mt][nt][0], acc[mt][nt][1]);
            float2 v1 = make_float2(acc[mt][nt][2], acc[mt][nt][3]);
            *(float2*)(C + (size_t)r * NDIM + col)       = v0;
            *(float2*)(C + (size_t)(r + 8) * NDIM + col) = v1;
            s8[nt][0] += v0.x + v1.x;
            s8[nt][1] += v0.y + v1.y;
            q8[nt][0] += v0.x * v0.x + v1.x * v1.x;
            q8[nt][1] += v0.y * v0.y + v1.y * v1.y;
        }
    }
    __syncthreads();
    #pragma unroll
    for (int nt = 0; nt < 4; nt++)
        #pragma unroll
        for (int j = 0; j < 2; j++) {
            float s = s8[nt][j], q = q8[nt][j];
            #pragma unroll
            for (int off = 4; off < 32; off <<= 1) {
                s += __shfl_xor_sync(0xFFFFFFFFu, s, off);
                q += __shfl_xor_sync(0xFFFFFFFFu, q, off);
            }
            if (lane < 4) {
                const int cl = wn * 32 + nt * 8 + lane * 2 + j;
                red_s[wm][cl] = s;
                red_q[wm][cl] = q;
            }
        }
    __syncthreads();
    if (tid < 128) {
        ps[(size_t)blockIdx.y * NDIM + n0 + tid] = red_s[0][tid] + red_s[1][tid];
        pq[(size_t)blockIdx.y * NDIM + n0 + tid] = red_q[0][tid] + red_q[1][tid];
    }
}

// ---------------- BN finalize v2: parallel 2-D reduction (32 ch x 8 slices) --------
__global__ __launch_bounds__(256) void finalize_kernel(
    const float* __restrict__ ps, const float* __restrict__ pq,
    const float* __restrict__ g, const float* __restrict__ be,
    float* __restrict__ sc, float* __restrict__ sh, int N)
{
    __shared__ float ss[8][33], sq[8][33];
    const int nl = threadIdx.x & 31;
    const int ig = threadIdx.x >> 5;           // 0..7
    const int n  = blockIdx.x * 32 + nl;
    float s = 0.0f, q = 0.0f;
    const int ibase = ig * (GRIDM / 8);        // 64 partials per slice
    #pragma unroll 8
    for (int i = 0; i < GRIDM / 8; i++) {
        s += ps[(size_t)(ibase + i) * N + n];
        q += pq[(size_t)(ibase + i) * N + n];
    }
    ss[ig][nl] = s; sq[ig][nl] = q;
    __syncthreads();
    if (ig == 0) {
        #pragma unroll
        for (int k = 1; k < 8; k++) { s += ss[k][nl]; q += sq[k][nl]; }
        const float mean = s * (1.0f / (float)MROWS);
        const float var  = q * (1.0f / (float)MROWS) - mean * mean;
        const float rstd = rsqrtf(var + 1e-5f);
        const float scale = g[n] * rstd;
        sc[n] = scale;
        sh[n] = be[n] - mean * scale;
    }
}

// ---------------- final BN+ReLU + transpose to [B, C3, NY] ----------------
__global__ __launch_bounds__(256) void output_kernel(
    const float* __restrict__ T3, const float* __restrict__ sc,
    const float* __restrict__ sh, float* __restrict__ out)
{
    __shared__ float tilebuf[32][33];
    const int mt = blockIdx.x * 32;
    const int ct = blockIdx.y * 32;
    const int tx = threadIdx.x;
    const int ty = threadIdx.y;
    #pragma unroll
    for (int i = ty; i < 32; i += 8) {
        const int c = ct + tx;
        const float v = T3[(size_t)(mt + i) * C3 + c];
        tilebuf[i][tx] = fmaxf(v * sc[c] + sh[c], 0.0f);
    }
    __syncthreads();
    const int m  = mt + tx;
    const int b  = m / NY;
    const int ny = m % NY;
    #pragma unroll
    for (int j = ty; j < 32; j += 8) {
        const int c = ct + j;
        out[((size_t)b * C3 + c) * NY + ny] = tilebuf[tx][j];
    }
}

// ---------------- launch ----------------
static void* sym_addr(const void* sym) { void* p = nullptr; cudaGetSymbolAddress(&p, sym); return p; }

extern "C" void kernel_launch(void* const* d_in, const int* in_sizes, int n_in,
                              void* d_out, int out_size)
{
    const float* y_points = (const float*)d_in[0];
    const float* y_feats  = (const float*)d_in[1];
    const float* x_points = (const float*)d_in[2];
    const float* x_feats  = (const float*)d_in[3];
    const float* W1 = (const float*)d_in[4];
    const float* g1 = (const float*)d_in[6];
    const float* be1= (const float*)d_in[7];
    const float* W2 = (const float*)d_in[8];
    const float* g2 = (const float*)d_in[10];
    const float* be2= (const float*)d_in[11];
    const float* W3 = (const float*)d_in[12];
    const float* g3 = (const float*)d_in[14];
    const float* be3= (const float*)d_in[15];
    float* out = (float*)d_out;
    // conv biases b1/b2/b3 cancel exactly through training-mode BN: mean shift
    // absorbs them and variance is unaffected, so they are intentionally unused.

    __half* pX = (__half*)sym_addr(g_X);
    float*  pT = (float*) sym_addr(g_T);
    float* pPs = (float*) sym_addr(g_ps);
    float* pPq = (float*) sym_addr(g_pq);
    float* pSc1= (float*) sym_addr(g_sc1);
    float* pSh1= (float*) sym_addr(g_sh1);
    float* pSc2= (float*) sym_addr(g_sc2);
    float* pSh2= (float*) sym_addr(g_sh2);
    float* pSc3= (float*) sym_addr(g_sc3);
    float* pSh3= (float*) sym_addr(g_sh3);
    __half* pW1h = (__half*)sym_addr(g_W1);
    __half* pW2h = (__half*)sym_addr(g_W2);
    __half* pW3h = (__half*)sym_addr(g_W3);

    constexpr int SMEMSZ = 3 * 2 * 128 * 144;   // 110592: 3 stages x (A, B)
    cudaFuncSetAttribute((const void*)hmma_gemm<DIM, C1>, cudaFuncAttributeMaxDynamicSharedMemorySize, SMEMSZ);
    cudaFuncSetAttribute((const void*)hmma_gemm<C1,  C2>, cudaFuncAttributeMaxDynamicSharedMemorySize, SMEMSZ);
    cudaFuncSetAttribute((const void*)hmma_gemm<C2,  C3>, cudaFuncAttributeMaxDynamicSharedMemorySize, SMEMSZ);

    // launch order puts hmma_gemm<384,512> at index 3 (the profiled slot)
    knn_gather_kernel<<<MROWS / 128, 512>>>(y_points, x_points, y_feats, x_feats, pX); // 0
    wconv_kernel<<<(C1 * DIM + 255) / 256, 256>>>(W1, pW1h, C1 * DIM);                 // 1
    wconv_kernel<<<(C2 * C1 + 255) / 256, 256>>>(W2, pW2h, C2 * C1);                   // 2
    hmma_gemm<DIM, C1><<<dim3(C1 / 128, GRIDM), 256, SMEMSZ>>>(pX, pW1h, pT, pPs, pPq);// 3 <- profiled
    wconv_kernel<<<(C3 * C2 + 255) / 256, 256>>>(W3, pW3h, C3 * C2);                   // 4
    finalize_kernel<<<C1 / 32, 256>>>(pPs, pPq, g1, be1, pSc1, pSh1, C1);              // 5
    bnconv_kernel<C1><<<(size_t)MROWS * C1 / 1024, 256>>>(pT, pSc1, pSh1, pX);         // 6
    hmma_gemm<C1, C2><<<dim3(C2 / 128, GRIDM), 256, SMEMSZ>>>(pX, pW2h, pT, pPs, pPq); // 7
    finalize_kernel<<<C2 / 32, 256>>>(pPs, pPq, g2, be2, pSc2, pSh2, C2);              // 8
    bnconv_kernel<C2><<<(size_t)MROWS * C2 / 1024, 256>>>(pT, pSc2, pSh2, pX);         // 9
    hmma_gemm<C2, C3><<<dim3(C3 / 128, GRIDM), 256, SMEMSZ>>>(pX, pW3h, pT, pPs, pPq); // 10
    finalize_kernel<<<C3 / 32, 256>>>(pPs, pPq, g3, be3, pSc3, pSh3, C3);              // 11
    output_kernel<<<dim3(MROWS / 32, C3 / 32), dim3(32, 8)>>>(pT, pSc3, pSh3, out);    // 12
}